// round 8
// baseline (speedup 1.0000x reference)
#include <cuda_runtime.h>
#include <cuda_fp16.h>
#include <cstdint>

// GraphAttentionLayer B=8,T=2048,D=256 — fp16 mma.sync.
//  K1: h = x@W^T, split-3 fp16, cp.async-pipelined (512 thr, 128 CTAs)
//  K2: attention, CTA tile 128x128, 256 thr, 2 CTAs/SM, 3-stage ring
//      (race-free ordering: wait+sync, then prefetch n+2, then mma n)

#define B_ 8
#define T_ 2048
#define NEG_SLOPE 0.2f

__device__ __half g_h[B_ * T_ * 256];   // [b][j][o], 8 MB
__device__ float g_s1[B_ * T_];
__device__ float g_s2[B_ * T_];

// ---------------- helpers ----------------------------------------------------
__device__ __forceinline__ uint32_t smem_u32(const void* p) {
  uint32_t a;
  asm("{ .reg .u64 t; cvta.to.shared.u64 t, %1; cvt.u32.u64 %0, t; }"
      : "=r"(a) : "l"(p));
  return a;
}
__device__ __forceinline__ void ldsm4(uint32_t addr, uint32_t r[4]) {
  asm volatile("ldmatrix.sync.aligned.m8n8.x4.shared.b16 {%0,%1,%2,%3}, [%4];"
               : "=r"(r[0]), "=r"(r[1]), "=r"(r[2]), "=r"(r[3]) : "r"(addr));
}
__device__ __forceinline__ void ldsm4t(uint32_t addr, uint32_t r[4]) {
  asm volatile("ldmatrix.sync.aligned.m8n8.x4.trans.shared.b16 {%0,%1,%2,%3}, [%4];"
               : "=r"(r[0]), "=r"(r[1]), "=r"(r[2]), "=r"(r[3]) : "r"(addr));
}
__device__ __forceinline__ void mma16816(float c[4], const uint32_t a[4],
                                         uint32_t b0, uint32_t b1) {
  asm volatile(
      "mma.sync.aligned.m16n8k16.row.col.f32.f16.f16.f32 "
      "{%0,%1,%2,%3}, {%4,%5,%6,%7}, {%8,%9}, {%0,%1,%2,%3};"
      : "+f"(c[0]), "+f"(c[1]), "+f"(c[2]), "+f"(c[3])
      : "r"(a[0]), "r"(a[1]), "r"(a[2]), "r"(a[3]), "r"(b0), "r"(b1));
}
__device__ __forceinline__ void cpa16(uint32_t dst, const void* src) {
  asm volatile("cp.async.cg.shared.global [%0], [%1], 16;" :: "r"(dst), "l"(src)
               : "memory");
}
#define CP_COMMIT() asm volatile("cp.async.commit_group;" ::: "memory")
#define CP_WAIT(n) asm volatile("cp.async.wait_group %0;" :: "n"(n) : "memory")

// split 8 fp32 -> hi,lo fp16x8
__device__ __forceinline__ void split8(const float* v, uint4& hi, uint4& lo) {
  uint32_t h[4], l[4];
#pragma unroll
  for (int q = 0; q < 4; q++) {
    float a = v[2 * q], b = v[2 * q + 1];
    __half ah = __float2half_rn(a), bh = __float2half_rn(b);
    __half2 hv; hv.x = ah; hv.y = bh; h[q] = *(uint32_t*)&hv;
    __half2 lv;
    lv.x = __float2half_rn(a - __half2float(ah));
    lv.y = __float2half_rn(b - __half2float(bh));
    l[q] = *(uint32_t*)&lv;
  }
  hi = make_uint4(h[0], h[1], h[2], h[3]);
  lo = make_uint4(l[0], l[1], l[2], l[3]);
}

// ============================================================================
// K1: h = x @ W^T. 128 CTAs, 512 threads, warp grid 4x4 (warp tile 32x64).
// K=256 in 4 chunks of 64. Split-3 fp16. cp.async fp32 staging, overlapped.
// ============================================================================
#define K1_FX 0                    // fp32 x tile [128][68]
#define K1_FW 34816                // fp32 W tile [256][68]
#define K1_AH 104448               // [128][72] fp16
#define K1_AL 122880
#define K1_BH 141312               // [256][72] fp16
#define K1_BL 178176
#define K1_AS 215040               // a[512] f32
#define K1_R1 217088               // [4][128] f32
#define K1_R2 219136
#define K1_SMEM 221184

__global__ __launch_bounds__(512, 1) void k1(
    const float* __restrict__ x, const float* __restrict__ W,
    const float* __restrict__ a) {
  extern __shared__ char sm[];
  const uint32_t SB = smem_u32(sm);
  const int t = threadIdx.x, lane = t & 31, wid = t >> 5;
  const int warpM = wid >> 2, warpN = wid & 3;
  const int i0 = blockIdx.x * 128;

#define K1_LOADF32(cc) do {                                                   \
    const int k0_ = (cc) * 64;                                                \
    _Pragma("unroll")                                                         \
    for (int v = 0; v < 4; v++) {                                             \
      int u = v * 512 + t, row = u >> 4, seg = u & 15;                        \
      cpa16(SB + K1_FX + (uint32_t)(row * 68 + seg * 4) * 4,                  \
            &x[(size_t)(i0 + row) * 256 + k0_ + seg * 4]);                    \
    }                                                                         \
    _Pragma("unroll")                                                         \
    for (int v = 0; v < 8; v++) {                                             \
      int u = v * 512 + t, row = u >> 4, seg = u & 15;                        \
      cpa16(SB + K1_FW + (uint32_t)(row * 68 + seg * 4) * 4,                  \
            &W[(size_t)row * 256 + k0_ + seg * 4]);                           \
    }                                                                         \
  } while (0)

  K1_LOADF32(0);
  CP_COMMIT();
  ((float*)(sm + K1_AS))[t] = a[t];

  float c[2][8][4];
#pragma unroll
  for (int r = 0; r < 2; r++)
#pragma unroll
    for (int f = 0; f < 8; f++)
#pragma unroll
      for (int q = 0; q < 4; q++) c[r][f][q] = 0.f;

  CP_WAIT(0);
  __syncthreads();

  for (int ch = 0; ch < 4; ch++) {
    // convert fp32 staging -> fp16 hi/lo tiles
    {
      const int row = t >> 2, quad = t & 3;
      float v[16];
#pragma unroll
      for (int q = 0; q < 4; q++)
        *(float4*)&v[q * 4] =
            *(const float4*)(sm + K1_FX + (uint32_t)(row * 68 + quad * 16 + q * 4) * 4);
      uint4 h0, l0, h1, l1;
      split8(v, h0, l0); split8(v + 8, h1, l1);
      const uint32_t off = (uint32_t)(row * 72 + quad * 16) * 2;
      *(uint4*)(sm + K1_AH + off) = h0; *(uint4*)(sm + K1_AH + off + 16) = h1;
      *(uint4*)(sm + K1_AL + off) = l0; *(uint4*)(sm + K1_AL + off + 16) = l1;
    }
    {
      const int row = t >> 1, half = (t & 1) * 32;
      float v[32];
#pragma unroll
      for (int q = 0; q < 8; q++)
        *(float4*)&v[q * 4] =
            *(const float4*)(sm + K1_FW + (uint32_t)(row * 68 + half + q * 4) * 4);
      const uint32_t off = (uint32_t)(row * 72 + half) * 2;
#pragma unroll
      for (int g = 0; g < 4; g++) {
        uint4 hh, ll;
        split8(v + g * 8, hh, ll);
        *(uint4*)(sm + K1_BH + off + g * 16) = hh;
        *(uint4*)(sm + K1_BL + off + g * 16) = ll;
      }
    }
    __syncthreads();
    if (ch < 3) { K1_LOADF32(ch + 1); CP_COMMIT(); }

#pragma unroll
    for (int ks = 0; ks < 64; ks += 16) {
      const uint32_t lrow = (uint32_t)(lane & 15);
      const uint32_t lcol = (uint32_t)(ks + ((lane >> 4) << 3));
      uint32_t ah[2][4], al[2][4];
#pragma unroll
      for (int r = 0; r < 2; r++) {
        uint32_t ra = SB + ((warpM * 32 + r * 16 + lrow) * 72 + lcol) * 2;
        ldsm4(ra + K1_AH, ah[r]);
        ldsm4(ra + K1_AL, al[r]);
      }
      uint32_t bh[8][2], bl[8][2];
#pragma unroll
      for (int q = 0; q < 4; q++) {
        uint32_t rb = SB + ((warpN * 64 + q * 16 + lrow) * 72 + lcol) * 2;
        uint32_t rr[4];
        ldsm4(rb + K1_BH, rr);
        bh[2 * q][0] = rr[0]; bh[2 * q + 1][0] = rr[1];
        bh[2 * q][1] = rr[2]; bh[2 * q + 1][1] = rr[3];
        ldsm4(rb + K1_BL, rr);
        bl[2 * q][0] = rr[0]; bl[2 * q + 1][0] = rr[1];
        bl[2 * q][1] = rr[2]; bl[2 * q + 1][1] = rr[3];
      }
#pragma unroll
      for (int r = 0; r < 2; r++)
#pragma unroll
        for (int f = 0; f < 8; f++) mma16816(c[r][f], ah[r], bh[f][0], bh[f][1]);
#pragma unroll
      for (int r = 0; r < 2; r++)
#pragma unroll
        for (int f = 0; f < 8; f++) mma16816(c[r][f], ah[r], bl[f][0], bl[f][1]);
#pragma unroll
      for (int r = 0; r < 2; r++)
#pragma unroll
        for (int f = 0; f < 8; f++) mma16816(c[r][f], al[r], bh[f][0], bh[f][1]);
    }
    CP_WAIT(0);
    __syncthreads();
  }

  // ---- epilogue: s1/s2 partials + h fp16 stores ----
  const float* as_ = (const float*)(sm + K1_AS);
  float s1p[4], s2p[4];
#pragma unroll
  for (int q = 0; q < 4; q++) { s1p[q] = 0.f; s2p[q] = 0.f; }
#pragma unroll
  for (int r = 0; r < 2; r++)
#pragma unroll
    for (int f = 0; f < 8; f++)
#pragma unroll
      for (int q = 0; q < 4; q++) {
        int col = warpN * 64 + f * 8 + 2 * (lane & 3) + (q & 1);
        int ri = r * 2 + (q >> 1);
        s1p[ri] += c[r][f][q] * as_[col];
        s2p[ri] += c[r][f][q] * as_[256 + col];
      }
#pragma unroll
  for (int o = 1; o < 4; o <<= 1)
#pragma unroll
    for (int ri = 0; ri < 4; ri++) {
      s1p[ri] += __shfl_xor_sync(0xffffffffu, s1p[ri], o);
      s2p[ri] += __shfl_xor_sync(0xffffffffu, s2p[ri], o);
    }
  if ((lane & 3) == 0) {
#pragma unroll
    for (int r = 0; r < 2; r++)
#pragma unroll
      for (int hh = 0; hh < 2; hh++) {
        int rowr = warpM * 32 + r * 16 + (lane >> 2) + hh * 8;
        ((float*)(sm + K1_R1))[warpN * 128 + rowr] = s1p[r * 2 + hh];
        ((float*)(sm + K1_R2))[warpN * 128 + rowr] = s2p[r * 2 + hh];
      }
  }
#pragma unroll
  for (int r = 0; r < 2; r++)
#pragma unroll
    for (int f = 0; f < 8; f++) {
      int row0 = i0 + warpM * 32 + r * 16 + (lane >> 2);
      int col0 = warpN * 64 + f * 8 + 2 * (lane & 3);
#pragma unroll
      for (int hh = 0; hh < 2; hh++) {
        size_t base = (size_t)(row0 + hh * 8) * 256 + col0;
        __half2 ph;
        ph.x = __float2half_rn(c[r][f][hh * 2]);
        ph.y = __float2half_rn(c[r][f][hh * 2 + 1]);
        *(uint32_t*)&g_h[base] = *(uint32_t*)&ph;
      }
    }
  __syncthreads();
  if (t < 128) {
    const float* r1 = (const float*)(sm + K1_R1);
    const float* r2 = (const float*)(sm + K1_R2);
    float v1 = 0.f, v2 = 0.f;
#pragma unroll
    for (int wn = 0; wn < 4; wn++) { v1 += r1[wn * 128 + t]; v2 += r2[wn * 128 + t]; }
    g_s1[i0 + t] = v1;
    g_s2[i0 + t] = v2;
  }
}

// ============================================================================
// K2: attention. 256 CTAs = 8 batch x 16 i-tiles x 2 n-halves. 256 threads,
// 2 CTAs/SM. CTA tile M=128, N=128, K=2048 in 32 chunks of 64.
// Warp grid 4(M) x 2(N), warp tile 32x64. 3-stage cp.async ring with
// race-free ordering: wait(1)+sync at top, prefetch n+2 (stage != n%3),
// then mma n. w fp16 on the fly (double-buffered); den from rounded w.
// ============================================================================
#define ATB 0                     // 3 stages x [64][136] fp16 = 17408 each
#define ATB_STG 17408
#define AT_A 52224                // 2 x [128][72] fp16 = 18432 each
#define AT_AST 18432
#define AT_S2 89088               // 2048 f32
#define AT_S1 97280               // 128 f32
#define AT_DB 97792               // 256 f32
#define AT_DEN 98816              // 128 f32
#define AT_SMEM 99328

__global__ __launch_bounds__(256, 2) void k2(float* __restrict__ out) {
  extern __shared__ char sm[];
  const uint32_t SB = smem_u32(sm);
  const int t = threadIdx.x, lane = t & 31, wid = t >> 5;
  const int warpM = wid >> 1, warpN = wid & 1;
  const int b = blockIdx.x >> 5;
  const int i0 = ((blockIdx.x >> 1) & 15) * 128;
  const int n0 = (blockIdx.x & 1) * 128;

  if (t < 128) ((float*)(sm + AT_S1))[t] = g_s1[b * 2048 + i0 + t];
#pragma unroll
  for (int j = t; j < 2048; j += 256)
    ((float*)(sm + AT_S2))[j] = g_s2[b * 2048 + j];
  __syncthreads();

  const float* s2s = (const float*)(sm + AT_S2);
  const int gm = t >> 1, gkh = (t & 1) * 32;   // w-gen: row gm, cols gkh..+31
  const float s1v = ((const float*)(sm + AT_S1))[gm];
  const __half* H = g_h + (size_t)b * 2048 * 256 + n0;

  float c[2][8][4];
#pragma unroll
  for (int r = 0; r < 2; r++)
#pragma unroll
    for (int f = 0; f < 8; f++)
#pragma unroll
      for (int q = 0; q < 4; q++) c[r][f][q] = 0.f;
  float dtot = 0.f;

#define GENW(nn, abuf) do {                                                   \
    const int j0_ = (nn) * 64;                                                \
    const uint32_t off_ = (uint32_t)(gm * 72 + gkh) * 2;                      \
_Pragma("unroll")                                                             \
    for (int g = 0; g < 4; g++) {                                             \
      float4 ea = *(const float4*)&s2s[j0_ + gkh + g * 8];                    \
      float4 eb = *(const float4*)&s2s[j0_ + gkh + g * 8 + 4];                \
      float ev[8] = {ea.x, ea.y, ea.z, ea.w, eb.x, eb.y, eb.z, eb.w};         \
      uint32_t pk_[4];                                                        \
_Pragma("unroll")                                                             \
      for (int q = 0; q < 4; q++) {                                           \
        float e0 = s1v + ev[2 * q];                                           \
        float e1 = s1v + ev[2 * q + 1];                                       \
        e0 = fmaxf(e0, NEG_SLOPE * e0);                                       \
        e1 = fmaxf(e1, NEG_SLOPE * e1);                                       \
        __half w0 = __float2half_rn(__expf(e0));                              \
        __half w1 = __float2half_rn(__expf(e1));                              \
        dtot += __half2float(w0) + __half2float(w1);                          \
        __half2 pp; pp.x = w0; pp.y = w1;                                     \
        pk_[q] = *(uint32_t*)&pp;                                             \
      }                                                                       \
      *(uint4*)((abuf) + off_ + g * 16) =                                     \
          make_uint4(pk_[0], pk_[1], pk_[2], pk_[3]);                         \
    }                                                                         \
  } while (0)

#define LOADB(nn) do {                                                        \
    const uint32_t dst_ = SB + ATB + ((nn) % 3) * ATB_STG;                    \
    const int j0_ = (nn) * 64;                                                \
_Pragma("unroll")                                                             \
    for (int v = 0; v < 4; v++) {                                             \
      int u = v * 256 + t, row = u >> 4, seg = u & 15;                        \
      cpa16(dst_ + (uint32_t)(row * 136 + seg * 8) * 2,                       \
            H + (size_t)(j0_ + row) * 256 + seg * 8);                        \
    }                                                                         \
  } while (0)

  // prologue: chunks 0,1 in flight; w(0) generated
  GENW(0, sm + AT_A);
  LOADB(0); CP_COMMIT();
  LOADB(1); CP_COMMIT();

  for (int n = 0; n < 32; n++) {
    const int p = n & 1;
    // chunk n guaranteed complete: commits so far = n+2, wait leaves <=1
    CP_WAIT(1);
    __syncthreads();
    // prefetch chunk n+2 -> stage (n+2)%3 != n%3; all warps are past the
    // sync, so chunk n-1's readers (same stage) are done. Always commit to
    // keep the wait(1) ledger exact.
    if (n + 2 < 32) LOADB(n + 2);
    CP_COMMIT();

    const uint32_t Bst = SB + ATB + (n % 3) * ATB_STG;
    const uint32_t Ab = SB + AT_A + p * AT_AST;

    // mma chunk n
#pragma unroll
    for (int ks = 0; ks < 64; ks += 16) {
      uint32_t ah[2][4];
#pragma unroll
      for (int r = 0; r < 2; r++)
        ldsm4(Ab + ((warpM * 32 + r * 16 + (lane & 15)) * 72 + ks +
                    ((lane >> 4) << 3)) * 2,
              ah[r]);
      const uint32_t roff =
          (uint32_t)(ks + ((lane >> 3) & 1) * 8 + (lane & 7)) * 136;
      uint32_t bh[8][2];
#pragma unroll
      for (int q = 0; q < 4; q++) {
        uint32_t coff = (uint32_t)(warpN * 64 + q * 16 + ((lane >> 4) << 3));
        uint32_t rr[4];
        ldsm4t(Bst + (roff + coff) * 2, rr);
        bh[2 * q][0] = rr[0]; bh[2 * q][1] = rr[1];
        bh[2 * q + 1][0] = rr[2]; bh[2 * q + 1][1] = rr[3];
      }
#pragma unroll
      for (int r = 0; r < 2; r++)
#pragma unroll
        for (int f = 0; f < 8; f++) mma16816(c[r][f], ah[r], bh[f][0], bh[f][1]);
    }

    // gen w for chunk n+1 into the other A buffer (readers gated by next sync)
    if (n < 31) GENW(n + 1, sm + AT_A + (p ^ 1) * AT_AST);
  }

  // ---- denominator + epilogue ----
  ((float*)(sm + AT_DB))[t] = dtot;
  __syncthreads();
  if (t < 128) {
    const float* db = (const float*)(sm + AT_DB);
    ((float*)(sm + AT_DEN))[t] = db[2 * t] + db[2 * t + 1];
  }
  __syncthreads();
  const float* den = (const float*)(sm + AT_DEN);
  float inv[4];
#pragma unroll
  for (int r = 0; r < 2; r++)
#pragma unroll
    for (int hh = 0; hh < 2; hh++)
      inv[r * 2 + hh] =
          1.0f / den[warpM * 32 + r * 16 + (lane >> 2) + hh * 8];

  float* ob = out + ((size_t)b * 2048 + i0) * 256 + n0;
#pragma unroll
  for (int r = 0; r < 2; r++)
#pragma unroll
    for (int f = 0; f < 8; f++) {
      int col = warpN * 64 + f * 8 + 2 * (lane & 3);
#pragma unroll
      for (int hh = 0; hh < 2; hh++) {
        int row = warpM * 32 + r * 16 + (lane >> 2) + hh * 8;
        float iv = inv[r * 2 + hh];
        float v0 = c[r][f][hh * 2] * iv;
        float v1 = c[r][f][hh * 2 + 1] * iv;
        v0 = v0 > 0.f ? v0 : expm1f(v0);
        v1 = v1 > 0.f ? v1 : expm1f(v1);
        *(float2*)&ob[(size_t)row * 256 + col] = make_float2(v0, v1);
      }
    }
}

// ============================================================================
extern "C" void kernel_launch(void* const* d_in, const int* in_sizes, int n_in,
                              void* d_out, int out_size) {
  (void)in_sizes; (void)n_in; (void)out_size;
  const float* x = (const float*)d_in[0];
  const float* W = (const float*)d_in[1];
  const float* a = (const float*)d_in[2];
  float* out = (float*)d_out;

  cudaFuncSetAttribute(k1, cudaFuncAttributeMaxDynamicSharedMemorySize, K1_SMEM);
  cudaFuncSetAttribute(k2, cudaFuncAttributeMaxDynamicSharedMemorySize, AT_SMEM);

  k1<<<128, 512, K1_SMEM>>>(x, W, a);
  k2<<<256, 256, AT_SMEM>>>(out);
}